// round 15
// baseline (speedup 1.0000x reference)
#include <cuda_runtime.h>
#include <cuda_bf16.h>
#include <math.h>
#include <stdint.h>

#define BB 4
#define TT 2048
#define VV 512
#define DD 256
#define HH 4
#define DHH 64
#define NBB 32
#define DFFN 1024
#define NL 2
#define EPSV 1e-5f
#define NTOK (BB*TT)
#define NS 2
#define QS (BB*HH*TT*DHH)

// ---------------- scratch ---------------------------------------------------
__device__ float g_x [NTOK*DD];
__device__ float g_h [NTOK*DD];
__device__ float g_qkv[3*QS];                // V stored TRANSPOSED [bh][dh][t]
__device__ float g_o [NTOK*DD];
__device__ float g_ff[NTOK*DFFN];
__device__ float g_r [NTOK*2];
__device__ float g_cos[BB*HH*TT*NBB];
__device__ float g_sin[BB*HH*TT*NBB];
__device__ float g_op[NS*BB*HH*TT*DHH];
__device__ float g_ml[NS*BB*HH*TT*2];

// weight buffer (tf32-rounded, weights TRANSPOSED to [N][K] for ldmatrix)
#define OFF_WQKV 0
#define OFF_WO   393216
#define OFF_W1   524288
#define OFF_W2   1048576
#define OFF_WOUT 1572864
#define OFF_BQKV 1703936
#define W_TOTAL  1705472
__device__ float g_wbuf[W_TOTAL];

#define CUMSUM_BLOCKS (BB*128)
#define PREP_BLOCKS   ((W_TOTAL + 255)/256)

// ---------------- helpers ----------------------------------------------------
__device__ __forceinline__ uint32_t f2t(float x) {
    uint32_t u; asm("cvt.rna.tf32.f32 %0, %1;" : "=r"(u) : "f"(x)); return u;
}
__device__ __forceinline__ float f2tf(float x) { return __uint_as_float(f2t(x)); }
__device__ __forceinline__ void mma8(float* c, const uint32_t* a, uint32_t b0, uint32_t b1) {
    asm volatile(
        "mma.sync.aligned.m16n8k8.row.col.f32.tf32.tf32.f32 "
        "{%0,%1,%2,%3}, {%4,%5,%6,%7}, {%8,%9}, {%0,%1,%2,%3};\n"
        : "+f"(c[0]), "+f"(c[1]), "+f"(c[2]), "+f"(c[3])
        : "r"(a[0]), "r"(a[1]), "r"(a[2]), "r"(a[3]), "r"(b0), "r"(b1));
}
#define LDSM4(r0, r1, r2, r3, addr) \
    asm volatile("ldmatrix.sync.aligned.m8n8.x4.shared.b16 {%0,%1,%2,%3}, [%4];" \
                 : "=r"(r0), "=r"(r1), "=r"(r2), "=r"(r3) : "r"(addr))
__device__ __forceinline__ void cp16(uint32_t* dst, const void* src) {
    uint32_t d = (uint32_t)__cvta_generic_to_shared(dst);
    asm volatile("cp.async.cg.shared.global [%0], [%1], 16;" :: "r"(d), "l"(src));
}
#define CP_COMMIT() asm volatile("cp.async.commit_group;")
#define CP_WAIT0()  asm volatile("cp.async.wait_group 0;")
#define CP_WAIT1()  asm volatile("cp.async.wait_group 1;")

// ---------------- fused embed + r + layer0-ln1 -------------------------------
__global__ void embed_r_ln_kernel(const int* __restrict__ tok, const float* __restrict__ emb,
                                  const float* __restrict__ w_in,
                                  const float* __restrict__ g, const float* __restrict__ bta,
                                  float* __restrict__ x, float* __restrict__ rr,
                                  float* __restrict__ h) {
    int warp = threadIdx.x >> 5, lane = threadIdx.x & 31;
    int m = blockIdx.x*8 + warp;
    int t = tok[m];
    const float* ep = emb + (size_t)t*DD;
    float* xp = x + (size_t)m*DD;
    float v[8]; float s = 0.f, p0 = 0.f, p1 = 0.f;
    #pragma unroll
    for (int i = 0; i < 8; i++) {
        int c = lane + i*32;
        float xv = ep[c];
        v[i] = xv;
        xp[c] = xv;
        s  += xv;
        p0 += xv * w_in[2*c];
        p1 += xv * w_in[2*c + 1];
    }
    #pragma unroll
    for (int off = 16; off > 0; off >>= 1) {
        s  += __shfl_xor_sync(0xffffffffu, s,  off);
        p0 += __shfl_xor_sync(0xffffffffu, p0, off);
        p1 += __shfl_xor_sync(0xffffffffu, p1, off);
    }
    if (lane == 0) { rr[m*2] = p0; rr[m*2+1] = p1; }
    float mu = s * (1.f/256.f);
    float q = 0.f;
    #pragma unroll
    for (int i = 0; i < 8; i++) { v[i] -= mu; q += v[i]*v[i]; }
    #pragma unroll
    for (int off = 16; off > 0; off >>= 1) q += __shfl_xor_sync(0xffffffffu, q, off);
    float inv = rsqrtf(q * (1.f/256.f) + EPSV);
    float* po = h + (size_t)m*DD;
    #pragma unroll
    for (int i = 0; i < 8; i++) {
        int c = lane + i*32;
        po[c] = f2tf(v[i]*inv*g[c] + bta[c]);
    }
}

// ---------------- fused prep(+transpose) + cumsum ----------------------------
__global__ void prep_cumsum_kernel(
    const float* __restrict__ rr, const float* __restrict__ w_out,
    const float* __restrict__ omega, float* __restrict__ cosb, float* __restrict__ sinb,
    const float* __restrict__ wq, const float* __restrict__ wk,
    const float* __restrict__ wv, const float* __restrict__ wo,
    const float* __restrict__ w1, const float* __restrict__ w2,
    const float* __restrict__ wout,
    const float* __restrict__ bq, const float* __restrict__ bk,
    const float* __restrict__ bv, float* __restrict__ dst) {
    if (blockIdx.x >= CUMSUM_BLOCKS) {
        int i = (blockIdx.x - CUMSUM_BLOCKS)*256 + threadIdx.x;
        if (i >= W_TOTAL) return;
        float v;
        if (i < OFF_WO) {                        // QKV [L][768][256] (n-major)
            int l = i / 196608, r = i % 196608;
            int n = r >> 8, k = r & 255;
            const float* s = (n < 256) ? wq : (n < 512) ? wk : wv;
            v = f2tf(s[((size_t)l*256 + k)*256 + (n & 255)]);
        } else if (i < OFF_W1) {                 // Wo [L][256][256] transposed
            int j = i - OFF_WO; int l = j >> 16, r = j & 65535;
            int n = r >> 8, k = r & 255;
            v = f2tf(wo[((size_t)l*256 + k)*256 + n]);
        } else if (i < OFF_W2) {                 // W1 [L][1024][256] transposed
            int j = i - OFF_W1; int l = j >> 18, r = j & 262143;
            int n = r >> 8, k = r & 255;
            v = f2tf(w1[((size_t)l*256 + k)*1024 + n]);
        } else if (i < OFF_WOUT) {               // W2 [L][256][1024] transposed
            int j = i - OFF_W2; int l = j >> 18, r = j & 262143;
            int n = r >> 10, k = r & 1023;
            v = f2tf(w2[((size_t)l*1024 + k)*256 + n]);
        } else if (i < OFF_BQKV) {               // Wout [512][256] transposed
            int j = i - OFF_WOUT;
            int n = j >> 8, k = j & 255;
            v = f2tf(wout[(size_t)k*512 + n]);
        } else {                                 // QKV bias interleaved (raw)
            int j = i - OFF_BQKV;
            int l = j / 768, n = j % 768;
            const float* s = (n < 256) ? bq : (n < 512) ? bk : bv;
            v = s[l*256 + (n & 255)];
        }
        dst[i] = v;
        return;
    }
    int bc = blockIdx.x;
    int b = bc >> 7, c = bc & 127;
    int h = c / NBB, nb = c % NBB;
    float om = omega[h*NBB + nb];
    float w0 = w_out[c], w1v = w_out[128 + c];
    int tid = threadIdx.x, lane = tid & 31, warp = tid >> 5;
    float v[8]; float s = 0.f;
    #pragma unroll
    for (int i = 0; i < 8; i++) {
        int t = tid*8 + i;
        float2 rv = *(const float2*)(rr + ((size_t)b*TT + t)*2);
        v[i] = rv.x*w0 + rv.y*w1v;
        s += v[i];
    }
    float sc = s;
    #pragma unroll
    for (int off = 1; off < 32; off <<= 1) {
        float n = __shfl_up_sync(0xffffffffu, sc, off);
        if (lane >= off) sc += n;
    }
    __shared__ float ws[8];
    if (lane == 31) ws[warp] = sc;
    __syncthreads();
    float woff = 0.f;
    for (int i = 0; i < warp; i++) woff += ws[i];
    float run = woff + sc - s;
    size_t base = (((size_t)b*HH + h)*TT)*NBB + nb;
    #pragma unroll
    for (int i = 0; i < 8; i++) {
        run += v[i];
        float ang = run * om;
        size_t idx = base + (size_t)(tid*8 + i)*NBB;
        cosb[idx] = cosf(ang);
        sinb[idx] = sinf(ang);
    }
}

// ---------------- layernorm --------------------------------------------------
__global__ void ln_kernel(const float* __restrict__ x, const float* __restrict__ g,
                          const float* __restrict__ bta, float* __restrict__ out) {
    int row  = blockIdx.x*8 + (threadIdx.x >> 5);
    int lane = threadIdx.x & 31;
    const float* p = x + (size_t)row*DD;
    float v[8]; float s = 0.f;
    #pragma unroll
    for (int i = 0; i < 8; i++) { v[i] = p[lane + i*32]; s += v[i]; }
    #pragma unroll
    for (int off = 16; off > 0; off >>= 1) s += __shfl_xor_sync(0xffffffffu, s, off);
    float mu = s * (1.f/256.f);
    float q = 0.f;
    #pragma unroll
    for (int i = 0; i < 8; i++) { v[i] -= mu; q += v[i]*v[i]; }
    #pragma unroll
    for (int off = 16; off > 0; off >>= 1) q += __shfl_xor_sync(0xffffffffu, q, off);
    float inv = rsqrtf(q * (1.f/256.f) + EPSV);
    float* po = out + (size_t)row*DD;
    #pragma unroll
    for (int i = 0; i < 8; i++) {
        int c = lane + i*32;
        po[c] = f2tf(v[i]*inv*g[c] + bta[c]);
    }
}

// ---------------- tf32 GEMM: CTA 128x128, warp tile 32x64, direct epilogue --
// A [M][K] row-major activations, Bt [N][K] n-major weights.
// MODE: 0 = QKV(rope/V-transpose), 1 = ADD, 2 = GELU+round, 3 = plain.
#define GST (2*128*36)                 // 9216 words per stage (A + B)
#define GSMEM (2*GST*4)                // 73728 bytes
template<int MODE>
__global__ void __launch_bounds__(256)
gemm_kernel(const float* __restrict__ A, const float* __restrict__ Bt,
            const float* __restrict__ bias, float* __restrict__ C,
            int M, int N, int K,
            const float* __restrict__ cosb, const float* __restrict__ sinb) {
    extern __shared__ uint32_t sb[];
    uint32_t smb = (uint32_t)__cvta_generic_to_shared(sb);
    int m0 = blockIdx.y * 128, n0 = blockIdx.x * 128;
    int tid = threadIdx.x, lane = tid & 31, warp = tid >> 5;
    int wm = warp >> 1, wn = warp & 1;
    float acc[2][8][4] = {};

#define GSTAGE(sp, k0v) do {                                                   \
    uint32_t* As_ = sb + (sp)*GST;                                             \
    uint32_t* Bs_ = As_ + 128*36;                                              \
    _Pragma("unroll")                                                          \
    for (int i_ = 0; i_ < 4; i_++) {                                           \
        int f_ = tid + i_*256;                                                 \
        int r_ = f_ >> 3, c_ = f_ & 7;                                         \
        cp16(As_ + r_*36 + c_*4, A  + (size_t)(m0+r_)*K + (k0v) + c_*4);       \
        cp16(Bs_ + r_*36 + c_*4, Bt + (size_t)(n0+r_)*K + (k0v) + c_*4);       \
    }                                                                          \
    CP_COMMIT();                                                               \
} while (0)

    GSTAGE(0, 0);
    for (int k0 = 0; k0 < K; k0 += 32) {
        int s = (k0 >> 5) & 1;
        bool pf = (k0 + 32 < K);
        if (pf) { GSTAGE(s^1, k0+32); CP_WAIT1(); }
        else    { CP_WAIT0(); }
        __syncthreads();
        uint32_t As_sh = smb + s*GST*4;
        uint32_t Bs_sh = As_sh + 128*36*4;
        #pragma unroll
        for (int ks = 0; ks < 4; ks++) {
            uint32_t af[2][4];
            #pragma unroll
            for (int mt = 0; mt < 2; mt++) {
                uint32_t row = wm*32 + mt*16 + (lane & 15);
                uint32_t col = ks*8 + ((lane & 16) ? 4 : 0);
                LDSM4(af[mt][0], af[mt][1], af[mt][2], af[mt][3],
                      As_sh + (row*36 + col)*4);
            }
            #pragma unroll
            for (int jp = 0; jp < 4; jp++) {
                uint32_t b0, b1, b2, b3;
                uint32_t row = wn*64 + jp*16 + (lane & 7) + ((lane & 16) ? 8 : 0);
                uint32_t col = ks*8 + ((lane & 8) ? 4 : 0);
                LDSM4(b0, b1, b2, b3, Bs_sh + (row*36 + col)*4);
                mma8(acc[0][2*jp],   af[0], b0, b1);
                mma8(acc[0][2*jp+1], af[0], b2, b3);
                mma8(acc[1][2*jp],   af[1], b0, b1);
                mma8(acc[1][2*jp+1], af[1], b2, b3);
            }
        }
        __syncthreads();
    }
#undef GSTAGE

    // direct-from-fragment epilogue
    int g = lane >> 2, t4 = lane & 3;
    #pragma unroll
    for (int mt = 0; mt < 2; mt++) {
        int r = m0 + wm*32 + mt*16 + g;          // rows r and r+8
        #pragma unroll
        for (int jn = 0; jn < 8; jn++) {
            int n = n0 + wn*64 + jn*8 + 2*t4;
            float bi0 = bias[n], bi1 = bias[n+1];
            float v0 = acc[mt][jn][0] + bi0, v1 = acc[mt][jn][1] + bi1;
            float v2 = acc[mt][jn][2] + bi0, v3 = acc[mt][jn][3] + bi1;
            if (MODE == 0) {
                int which = n >> 8;
                int h = (n >> 6) & 3;
                int b0i = r >> 11, t0i = r & 2047;
                int b1i = (r+8) >> 11, t1i = (r+8) & 2047;
                if (which == 2) {
                    int dh = n & 63;
                    float* base = C + (size_t)2*QS;
                    size_t c0 = ((size_t)(b0i*HH + h)*DHH + dh)*TT;
                    size_t c1 = ((size_t)(b1i*HH + h)*DHH + dh)*TT;
                    base[c0 + t0i]      = f2tf(v0);
                    base[c0 + TT + t0i] = f2tf(v1);
                    base[c1 + t1i]      = f2tf(v2);
                    base[c1 + TT + t1i] = f2tf(v3);
                } else {
                    int pc = (n & 63) >> 1;
                    float* base = C + (size_t)which*QS;
                    size_t ci0 = (((size_t)b0i*HH + h)*TT + t0i)*NBB + pc;
                    size_t ci1 = (((size_t)b1i*HH + h)*TT + t1i)*NBB + pc;
                    float c0 = cosb[ci0], s0 = sinb[ci0];
                    float c1 = cosb[ci1], s1 = sinb[ci1];
                    float o0 = v0*c0 - v1*s0, o1 = v0*s0 + v1*c0;
                    float o2 = v2*c1 - v3*s1, o3 = v2*s1 + v3*c1;
                    if (which == 0) { o0 *= 0.125f; o1 *= 0.125f; o2 *= 0.125f; o3 *= 0.125f; }
                    *(float2*)(base + (((size_t)b0i*HH + h)*TT + t0i)*DHH + (n & 63)) =
                        make_float2(f2tf(o0), f2tf(o1));
                    *(float2*)(base + (((size_t)b1i*HH + h)*TT + t1i)*DHH + (n & 63)) =
                        make_float2(f2tf(o2), f2tf(o3));
                }
            } else {
                size_t i0 = (size_t)r*N + n;
                size_t i1 = (size_t)(r+8)*N + n;
                if (MODE == 1) {
                    float2 a0 = *(float2*)(C + i0);
                    float2 a1 = *(float2*)(C + i1);
                    *(float2*)(C + i0) = make_float2(a0.x + v0, a0.y + v1);
                    *(float2*)(C + i1) = make_float2(a1.x + v2, a1.y + v3);
                } else if (MODE == 2) {
                    float g0 = 0.5f*v0*(1.f + erff(v0*0.70710678118654752f));
                    float g1 = 0.5f*v1*(1.f + erff(v1*0.70710678118654752f));
                    float g2 = 0.5f*v2*(1.f + erff(v2*0.70710678118654752f));
                    float g3 = 0.5f*v3*(1.f + erff(v3*0.70710678118654752f));
                    *(float2*)(C + i0) = make_float2(f2tf(g0), f2tf(g1));
                    *(float2*)(C + i1) = make_float2(f2tf(g2), f2tf(g3));
                } else {
                    *(float2*)(C + i0) = make_float2(v0, v1);
                    *(float2*)(C + i1) = make_float2(v2, v3);
                }
            }
        }
    }
}

// ---------------- flash attention, split-KV + ldmatrix (R14) -----------------
#define FKV 4352
#define FSMEM ((128*68 + 4*FKV)*4)
__global__ void __launch_bounds__(256)
flash_kernel(const float* __restrict__ Q, const float* __restrict__ K,
             const float* __restrict__ V, float* __restrict__ op,
             float* __restrict__ ml) {
    extern __shared__ uint32_t sm[];
    uint32_t smb = (uint32_t)__cvta_generic_to_shared(sm);
    uint32_t* Ps  = sm;
    uint32_t* Ksm = sm + 128*68;
    uint32_t* Vsm = Ksm + 2*FKV;
    uint32_t Ps_sh = smb;
    uint32_t Ks_sh = smb + 128*68*4;
    uint32_t Vs_sh = Ks_sh + 2*FKV*4;
    int qt = (gridDim.x - 1) - blockIdx.x;
    int bh = blockIdx.y;
    int s_id = blockIdx.z;
    int tid = threadIdx.x, lane = tid & 31, warp = tid >> 5;
    int g = lane >> 2, t4 = lane & 3;
    const float* Qp = Q + (size_t)bh*TT*DHH + (size_t)qt*128*DHH;
    const float* Kp = K + (size_t)bh*TT*DHH;
    const float* Vp = V + (size_t)bh*TT*DHH;    // transposed [dh][t]

#define STAGE_KV(sp, ktv) do {                                        \
    const float* kp_ = Kp + (size_t)(ktv)*64*DHH;                     \
    _Pragma("unroll")                                                 \
    for (int i_ = 0; i_ < 4; i_++) {                                  \
        int f_ = tid + i_*256;                                        \
        int r_ = f_ >> 4, c_ = f_ & 15;                               \
        cp16(Ksm + (sp)*FKV + r_*68 + c_*4, kp_ + r_*64 + c_*4);      \
        cp16(Vsm + (sp)*FKV + r_*68 + c_*4,                           \
             Vp + (size_t)r_*TT + (ktv)*64 + c_*4);                   \
    }                                                                 \
    CP_COMMIT();                                                      \
} while (0)

    #pragma unroll
    for (int i = 0; i < 8; i++) {
        int f = tid + i*256;
        int r = f >> 4, c4 = f & 15;
        cp16(Ps + r*68 + c4*4, Qp + r*64 + c4*4);
    }
    CP_COMMIT();
    int ktend = 2*qt + 1;
    STAGE_KV(0, s_id);
    CP_WAIT1();
    __syncthreads();

    int r0 = warp*16 + g;
    uint32_t qf[8][4];
    #pragma unroll
    for (int ds = 0; ds < 8; ds++) {
        uint32_t row = warp*16 + (lane & 15);
        uint32_t col = ds*8 + ((lane & 16) ? 4 : 0);
        LDSM4(qf[ds][0], qf[ds][1], qf[ds][2], qf[ds][3], Ps_sh + (row*68 + col)*4);
    }

    float accO[8][4] = {};
    float m0 = -1e30f, m1 = -1e30f, l0 = 0.f, l1 = 0.f;

    int it = 0;
    for (int kt = s_id; kt <= ktend; kt += NS, it++) {
        int s = it & 1;
        bool pf = (kt + NS <= ktend);
        if (pf) { STAGE_KV(s^1, kt+NS); CP_WAIT1(); }
        else    { CP_WAIT0(); }
        __syncthreads();

        bool act = (kt*64 <= qt*128 + warp*16 + 15);
        if (act) {
            uint32_t Kb = Ks_sh + s*FKV*4;
            uint32_t Vb = Vs_sh + s*FKV*4;

            float sc[8][4] = {};
            #pragma unroll
            for (int ds = 0; ds < 8; ds++) {
                #pragma unroll
                for (int jp = 0; jp < 4; jp++) {
                    uint32_t b0, b1, b2, b3;
                    uint32_t row = jp*16 + (lane & 7) + ((lane & 16) ? 8 : 0);
                    uint32_t col = ds*8 + ((lane & 8) ? 4 : 0);
                    LDSM4(b0, b1, b2, b3, Kb + (row*68 + col)*4);
                    mma8(sc[2*jp],   qf[ds], b0, b1);
                    mma8(sc[2*jp+1], qf[ds], b2, b3);
                }
            }

            float tm0 = -1e30f, tm1 = -1e30f;
            bool needmask = (kt >= 2*qt);
            #pragma unroll
            for (int j = 0; j < 8; j++)
                #pragma unroll
                for (int c = 0; c < 4; c++) {
                    float v = sc[j][c];
                    if (needmask) {
                        int col = kt*64 + j*8 + 2*t4 + (c & 1);
                        int row = qt*128 + warp*16 + g + ((c>>1)?8:0);
                        if (col > row) v = -1e30f;
                    }
                    sc[j][c] = v;
                    if (c < 2) tm0 = fmaxf(tm0, v); else tm1 = fmaxf(tm1, v);
                }
            tm0 = fmaxf(tm0, __shfl_xor_sync(0xffffffffu, tm0, 1));
            tm0 = fmaxf(tm0, __shfl_xor_sync(0xffffffffu, tm0, 2));
            tm1 = fmaxf(tm1, __shfl_xor_sync(0xffffffffu, tm1, 1));
            tm1 = fmaxf(tm1, __shfl_xor_sync(0xffffffffu, tm1, 2));
            float mn0 = fmaxf(m0, tm0), mn1 = fmaxf(m1, tm1);
            float a0 = __expf(m0 - mn0), a1 = __expf(m1 - mn1);
            float rs0 = 0.f, rs1 = 0.f;
            #pragma unroll
            for (int j = 0; j < 8; j++)
                #pragma unroll
                for (int c = 0; c < 4; c++) {
                    float p = __expf(sc[j][c] - ((c < 2) ? mn0 : mn1));
                    sc[j][c] = p;
                    if (c < 2) rs0 += p; else rs1 += p;
                }
            rs0 += __shfl_xor_sync(0xffffffffu, rs0, 1);
            rs0 += __shfl_xor_sync(0xffffffffu, rs0, 2);
            rs1 += __shfl_xor_sync(0xffffffffu, rs1, 1);
            rs1 += __shfl_xor_sync(0xffffffffu, rs1, 2);
            l0 = l0*a0 + rs0; l1 = l1*a1 + rs1;
            m0 = mn0; m1 = mn1;
            #pragma unroll
            for (int j = 0; j < 8; j++) {
                accO[j][0] *= a0; accO[j][1] *= a0;
                accO[j][2] *= a1; accO[j][3] *= a1;
            }

            // P (tf32) into warp-private rows of Ps
            #pragma unroll
            for (int j = 0; j < 8; j++) {
                Ps[r0*68     + j*8 + 2*t4    ] = f2t(sc[j][0]);
                Ps[r0*68     + j*8 + 2*t4 + 1] = f2t(sc[j][1]);
                Ps[(r0+8)*68 + j*8 + 2*t4    ] = f2t(sc[j][2]);
                Ps[(r0+8)*68 + j*8 + 2*t4 + 1] = f2t(sc[j][3]);
            }
            __syncwarp();

            // O += P @ V  (V^T is n-major for ldmatrix)
            #pragma unroll
            for (int ks = 0; ks < 8; ks++) {
                uint32_t a[4];
                {
                    uint32_t row = warp*16 + (lane & 15);
                    uint32_t col = ks*8 + ((lane & 16) ? 4 : 0);
                    LDSM4(a[0], a[1], a[2], a[3], Ps_sh + (row*68 + col)*4);
                }
                #pragma unroll
                for (int jp = 0; jp < 4; jp++) {
                    uint32_t b0, b1, b2, b3;
                    uint32_t row = jp*16 + (lane & 7) + ((lane & 16) ? 8 : 0);
                    uint32_t col = ks*8 + ((lane & 8) ? 4 : 0);
                    LDSM4(b0, b1, b2, b3, Vb + (row*68 + col)*4);
                    mma8(accO[2*jp],   a, b0, b1);
                    mma8(accO[2*jp+1], a, b2, b3);
                }
            }
        }
        __syncthreads();
    }
#undef STAGE_KV

    size_t ro = ((size_t)s_id*HH*BB + bh)*TT + qt*128 + warp*16 + g;
    if (t4 == 0) {
        ml[ro*2]       = m0; ml[ro*2 + 1]       = l0;
        ml[(ro+8)*2]   = m1; ml[(ro+8)*2 + 1]   = l1;
    }
    #pragma unroll
    for (int jd = 0; jd < 8; jd++) {
        int dh0 = jd*8 + 2*t4;
        float* p0 = op + ro*DHH + dh0;
        float* p1 = op + (ro+8)*DHH + dh0;
        p0[0] = accO[jd][0]; p0[1] = accO[jd][1];
        p1[0] = accO[jd][2]; p1[1] = accO[jd][3];
    }
}

// ---------------- combine split partials -> O (B,T,D) -----------------------
__global__ void combine_kernel(const float* __restrict__ op, const float* __restrict__ ml,
                               float* __restrict__ O) {
    int idx = blockIdx.x*256 + threadIdx.x;
    int dh = idx & 63;
    int row = idx >> 6;
    int bh = row >> 11, t = row & 2047;
    const int RTOT = BB*HH*TT;
    float mA = ml[(size_t)row*2],          lA = ml[(size_t)row*2 + 1];
    float mB = ml[((size_t)RTOT + row)*2], lB = ml[((size_t)RTOT + row)*2 + 1];
    float m = fmaxf(mA, mB);
    float wA = (mA < -1e29f) ? 0.f : __expf(mA - m);
    float wB = (mB < -1e29f) ? 0.f : __expf(mB - m);
    float inv = 1.f / (wA*lA + wB*lB);
    float v = (wA*op[(size_t)row*DHH + dh] + wB*op[((size_t)RTOT + row)*(size_t)DHH + dh]) * inv;
    int b = bh >> 2, h = bh & 3;
    O[((size_t)b*TT + t)*DD + h*DHH + dh] = f2tf(v);
}

// ---------------- host orchestration ----------------------------------------
extern "C" void kernel_launch(void* const* d_in, const int* in_sizes, int n_in,
                              void* d_out, int out_size) {
    const int*   tokens    = (const int*)  d_in[0];
    const float* token_emb = (const float*)d_in[1];
    const float* w_in      = (const float*)d_in[2];
    const float* w_out     = (const float*)d_in[3];
    const float* omega     = (const float*)d_in[4];
    const float* Wq  = (const float*)d_in[5];
    const float* bq  = (const float*)d_in[6];
    const float* Wk  = (const float*)d_in[7];
    const float* bk  = (const float*)d_in[8];
    const float* Wv  = (const float*)d_in[9];
    const float* bv  = (const float*)d_in[10];
    const float* Wo  = (const float*)d_in[11];
    const float* bo  = (const float*)d_in[12];
    const float* ln1_g = (const float*)d_in[13];
    const float* ln1_b = (const float*)d_in[14];
    const float* ln2_g = (const float*)d_in[15];
    const float* ln2_b = (const float*)d_in[16];
    const float* W1  = (const float*)d_in[17];
    const float* b1  = (const float*)d_in[18];
    const float* W2  = (const float*)d_in[19];
    const float* b2  = (const float*)d_in[20];
    const float* out_g = (const float*)d_in[21];
    const float* out_b = (const float*)d_in[22];
    const float* Wout  = (const float*)d_in[23];
    const float* bout  = (const float*)d_in[24];
    float* out = (float*)d_out;

    float *x, *h, *qkv, *o, *ff, *rr, *cs, *sn, *wb, *op, *ml;
    cudaGetSymbolAddress((void**)&x,   g_x);
    cudaGetSymbolAddress((void**)&h,   g_h);
    cudaGetSymbolAddress((void**)&qkv, g_qkv);
    cudaGetSymbolAddress((void**)&o,   g_o);
    cudaGetSymbolAddress((void**)&ff,  g_ff);
    cudaGetSymbolAddress((void**)&rr,  g_r);
    cudaGetSymbolAddress((void**)&cs,  g_cos);
    cudaGetSymbolAddress((void**)&sn,  g_sin);
    cudaGetSymbolAddress((void**)&wb,  g_wbuf);
    cudaGetSymbolAddress((void**)&op,  g_op);
    cudaGetSymbolAddress((void**)&ml,  g_ml);

    static int attr_set = 0;
    if (!attr_set) {
        cudaFuncSetAttribute(flash_kernel, cudaFuncAttributeMaxDynamicSharedMemorySize, FSMEM);
        cudaFuncSetAttribute(gemm_kernel<0>, cudaFuncAttributeMaxDynamicSharedMemorySize, GSMEM);
        cudaFuncSetAttribute(gemm_kernel<1>, cudaFuncAttributeMaxDynamicSharedMemorySize, GSMEM);
        cudaFuncSetAttribute(gemm_kernel<2>, cudaFuncAttributeMaxDynamicSharedMemorySize, GSMEM);
        cudaFuncSetAttribute(gemm_kernel<3>, cudaFuncAttributeMaxDynamicSharedMemorySize, GSMEM);
        attr_set = 1;
    }

    embed_r_ln_kernel<<<NTOK/8, 256>>>(tokens, token_emb, w_in, ln1_g, ln1_b, x, rr, h);
    prep_cumsum_kernel<<<CUMSUM_BLOCKS + PREP_BLOCKS, 256>>>(
        rr, w_out, omega, cs, sn, Wq, Wk, Wv, Wo, W1, W2, Wout, bq, bk, bv, wb);

    const int M = NTOK;   // 8192
    for (int i = 0; i < NL; i++) {
        if (i > 0)
            ln_kernel<<<NTOK/8, 256>>>(x, ln1_g + i*DD, ln1_b + i*DD, h);
        gemm_kernel<0><<<dim3(768/128, M/128), 256, GSMEM>>>(
            h, wb + OFF_WQKV + (size_t)i*196608, wb + OFF_BQKV + i*768, qkv, M, 768, 256, cs, sn);
        flash_kernel<<<dim3(TT/128, BB*HH, NS), 256, FSMEM>>>(qkv, qkv + QS, qkv + 2*QS, op, ml);
        combine_kernel<<<BB*HH*TT*DHH/256, 256>>>(op, ml, o);
        gemm_kernel<1><<<dim3(DD/128, M/128), 256, GSMEM>>>(
            o, wb + OFF_WO + (size_t)i*DD*DD, bo + i*DD, x, M, DD, DD, nullptr, nullptr);
        ln_kernel<<<NTOK/8, 256>>>(x, ln2_g + i*DD, ln2_b + i*DD, h);
        gemm_kernel<2><<<dim3(DFFN/128, M/128), 256, GSMEM>>>(
            h, wb + OFF_W1 + (size_t)i*DD*DFFN, b1 + i*DFFN, ff, M, DFFN, DD, nullptr, nullptr);
        gemm_kernel<1><<<dim3(DD/128, M/128), 256, GSMEM>>>(
            ff, wb + OFF_W2 + (size_t)i*DFFN*DD, b2 + i*DD, x, M, DD, DFFN, nullptr, nullptr);
    }
    ln_kernel<<<NTOK/8, 256>>>(x, out_g, out_b, h);
    gemm_kernel<3><<<dim3(VV/128, M/128), 256, GSMEM>>>(
        h, wb + OFF_WOUT, bout, out, M, VV, DD, nullptr, nullptr);
}